// round 15
// baseline (speedup 1.0000x reference)
#include <cuda_runtime.h>

#define NN 50000
#define NE 1600000
#define NG 512
#define NL 3
#define D 128
#define EF 16
#define BN_EPS 1e-5f
#define NPADMAX (NE + 4 * NN)   // slots, offsets padded to multiples of 4
#define NBLK 49                 // ceil(NN/1024)

// Scratch (device globals: allocation-free rule)
__device__ float g_h[NN * D];
__device__ float g_z[NN * D];
__device__ float g_pool[NG * NL * D];
__device__ int   g_deg[NN];
__device__ int   g_off[NN + 1];     // padded (mult-of-4) segment starts
__device__ int   g_cursor[NN];
__device__ int   g_eid[NPADMAX];
__device__ int   g_src[NPADMAX];
__device__ float g_attr[(size_t)NPADMAX * EF];   // attr permuted to CSR order
__device__ int   g_bsum[NBLK];
__device__ int   g_boff[NBLK];

// ---------------------------------------------------------------------------
// CSR build
// ---------------------------------------------------------------------------
__global__ void hist_kernel(const int* __restrict__ ei)
{
    int e = blockIdx.x * blockDim.x + threadIdx.x;
    if (e < NE) atomicAdd(&g_deg[ei[NE + e]], 1);
}

// phase 1: per-1024-chunk exclusive scan of padded degrees
__global__ void scan1_kernel()
{
    __shared__ int buf[1024];
    const int tid = threadIdx.x;
    const int i = blockIdx.x * 1024 + tid;
    const int v = (i < NN) ? ((g_deg[i] + 3) & ~3) : 0;
    buf[tid] = v;
    __syncthreads();
    for (int o = 1; o < 1024; o <<= 1) {
        int t = (tid >= o) ? buf[tid - o] : 0;
        __syncthreads();
        buf[tid] += t;
        __syncthreads();
    }
    if (i < NN) g_off[i] = buf[tid] - v;
    if (tid == 1023) g_bsum[blockIdx.x] = buf[1023];
}

// phase 2: warp scan of the 49 block sums
__global__ void scan2_kernel()
{
    const int tid = threadIdx.x;   // 32 threads
    const int v0 = (2 * tid < NBLK) ? g_bsum[2 * tid] : 0;
    const int v1 = (2 * tid + 1 < NBLK) ? g_bsum[2 * tid + 1] : 0;
    const int ps = v0 + v1;
    int x = ps;
    for (int o = 1; o < 32; o <<= 1) {
        int t = __shfl_up_sync(0xffffffffu, x, o);
        if (tid >= o) x += t;
    }
    const int excl = x - ps;
    if (2 * tid < NBLK) g_boff[2 * tid] = excl;
    if (2 * tid + 1 < NBLK) g_boff[2 * tid + 1] = excl + v0;
    if (tid == 31) g_off[NN] = x;   // total padded slots
}

// phase 3: add block offsets
__global__ void scan3_kernel()
{
    int i = blockIdx.x * 1024 + threadIdx.x;
    if (i < NN) g_off[i] += g_boff[blockIdx.x];
}

__global__ void fill_kernel(const int* __restrict__ ei)
{
    int e = blockIdx.x * blockDim.x + threadIdx.x;
    if (e < NE) {
        int pos = atomicAdd(&g_cursor[ei[NE + e]], 1);
        g_eid[pos] = e;
        g_src[pos] = ei[e];
    }
}

// Permute edge_attr into CSR slot order (64 B/slot, no duplication).
// 4 threads per slot, one float4 each. Pad slots read eid=0 (deterministic).
__global__ void permute_kernel(const float* __restrict__ edge_attr)
{
    const int idx = blockIdx.x * blockDim.x + threadIdx.x;
    const int slot = idx >> 2;
    const int q = idx & 3;
    if (slot >= g_off[NN]) return;
    const int e = g_eid[slot];
    const float4 a = __ldg((const float4*)(edge_attr + (size_t)e * EF) + q);
    ((float4*)(g_attr + (size_t)slot * EF))[q] = a;
}

// ---------------------------------------------------------------------------
// Aggregation: TWO warps per node (64 dims each), 4-edge groups.
//   z[n] = h[n] + sum_e relu(h[src(e)] + attr(e) @ elW + elb)
// src: sequential aligned int4. attr: uniform LDG.128 (L1 broadcast).
// Lane owns 2 dims (float2); wr = 16x2 regs -> ~75 regs -> 24 warps/SM.
// ---------------------------------------------------------------------------
#define EDGE_COMPUTE2(hv, slot)                                               \
    {                                                                         \
        const float4* ap = (const float4*)(g_attr + (size_t)(slot) * EF);     \
        const float4 q0 = __ldg(ap + 0);                                      \
        const float4 q1 = __ldg(ap + 1);                                      \
        const float4 q2 = __ldg(ap + 2);                                      \
        const float4 q3 = __ldg(ap + 3);                                      \
        float e0 = br0, e1 = br1;                                             \
        const float a[EF] = { q0.x, q0.y, q0.z, q0.w, q1.x, q1.y, q1.z, q1.w,\
                              q2.x, q2.y, q2.z, q2.w, q3.x, q3.y, q3.z, q3.w };\
        _Pragma("unroll")                                                     \
        for (int f = 0; f < EF; f++) {                                        \
            e0 += a[f] * wr[f][0];                                            \
            e1 += a[f] * wr[f][1];                                            \
        }                                                                     \
        accx += fmaxf((hv).x + e0, 0.0f);                                     \
        accy += fmaxf((hv).y + e1, 0.0f);                                     \
    }

__global__ void __launch_bounds__(256, 3) aggr_kernel(
    const float* __restrict__ h,
    const float* __restrict__ elW,   // [EF, D] this layer
    const float* __restrict__ elb)   // [D]
{
    const int lane = threadIdx.x & 31;
    const int gw = blockIdx.x * 8 + (threadIdx.x >> 5);
    const int n = gw >> 1;            // node
    const int off = ((gw & 1) << 6) + lane * 2;   // dim offset: half*64 + lane*2
    if (n >= NN) return;

    float wr[EF][2];
#pragma unroll
    for (int f = 0; f < EF; f++) {
        const float2 w = *(const float2*)(elW + f * D + off);
        wr[f][0] = w.x; wr[f][1] = w.y;
    }
    const float2 bb = *(const float2*)(elb + off);
    const float br0 = bb.x, br1 = bb.y;

    const int beg = g_off[n];          // multiple of 4
    const int end = beg + g_deg[n];
    float accx = 0.f, accy = 0.f;

    int idx = beg;
    for (; idx + 4 <= end; idx += 4) {
        const int4 sp = *(const int4*)(g_src + idx);
        const float2 hv0 = __ldg((const float2*)(h + (size_t)sp.x * D + off));
        const float2 hv1 = __ldg((const float2*)(h + (size_t)sp.y * D + off));
        const float2 hv2 = __ldg((const float2*)(h + (size_t)sp.z * D + off));
        const float2 hv3 = __ldg((const float2*)(h + (size_t)sp.w * D + off));
        EDGE_COMPUTE2(hv0, idx + 0);
        EDGE_COMPUTE2(hv1, idx + 1);
        EDGE_COMPUTE2(hv2, idx + 2);
        EDGE_COMPUTE2(hv3, idx + 3);
    }
    for (; idx < end; idx++) {
        const int src = g_src[idx];
        const float2 hv = __ldg((const float2*)(h + (size_t)src * D + off));
        EDGE_COMPUTE2(hv, idx);
    }

    const float2 hn = __ldg((const float2*)(h + (size_t)n * D + off));
    float2 z; z.x = accx + hn.x; z.y = accy + hn.y;
    *(float2*)(g_z + (size_t)n * D + off) = z;
}

// ---------------------------------------------------------------------------
// Node MLP: register-blocked, 8 nodes per warp. BN folded into W1/b1.
// ---------------------------------------------------------------------------
__global__ void __launch_bounds__(512) node_kernel(
    const float* __restrict__ W1, const float* __restrict__ b1,
    const float* __restrict__ bng, const float* __restrict__ bnb,
    const float* __restrict__ bnm, const float* __restrict__ bnv,
    const float* __restrict__ W2, const float* __restrict__ b2,
    const int* __restrict__ batch,
    int layer)
{
    extern __shared__ float sm[];
    float* W1f = sm;
    float* W2s = sm + D * D;
    float* b1f = W2s + D * D;
    float* b2s = b1f + D;
    float* scl = b2s + D;
    float* zbuf = scl + D;

    const int tid = threadIdx.x;

    for (int j = tid; j < D; j += blockDim.x) {
        const float s = bng[j] * rsqrtf(bnv[j] + BN_EPS);
        scl[j] = s;
        b1f[j] = b1[j] * s + (bnb[j] - bnm[j] * s);
        b2s[j] = b2[j];
    }
    __syncthreads();
    for (int i = tid; i < D * D; i += blockDim.x) {
        W1f[i] = W1[i] * scl[i & (D - 1)];
        W2s[i] = W2[i];
    }
    __syncthreads();

    const int lane = tid & 31;
    const int warp = tid >> 5;
    float* zb = zbuf + warp * 8 * D;

    const int gw = blockIdx.x * 16 + warp;
    const int nw = gridDim.x * 16;

    for (int base = gw * 8; base < NN; base += nw * 8) {
#pragma unroll
        for (int i = 0; i < 8; i++) {
            const float4 v = __ldg((const float4*)(g_z + (size_t)(base + i) * D) + lane);
            ((float4*)(zb + i * D))[lane] = v;
        }
        __syncwarp();

        float4 acc[8];
        {
            const float4 bb = ((const float4*)b1f)[lane];
#pragma unroll
            for (int i = 0; i < 8; i++) acc[i] = bb;
        }
#pragma unroll 4
        for (int k = 0; k < D; k += 4) {
            const float4 w0 = ((const float4*)(W1f + (k + 0) * D))[lane];
            const float4 w1 = ((const float4*)(W1f + (k + 1) * D))[lane];
            const float4 w2 = ((const float4*)(W1f + (k + 2) * D))[lane];
            const float4 w3 = ((const float4*)(W1f + (k + 3) * D))[lane];
#pragma unroll
            for (int i = 0; i < 8; i++) {
                const float4 zv = *(const float4*)(zb + i * D + k);
                acc[i].x += zv.x * w0.x + zv.y * w1.x + zv.z * w2.x + zv.w * w3.x;
                acc[i].y += zv.x * w0.y + zv.y * w1.y + zv.z * w2.y + zv.w * w3.y;
                acc[i].z += zv.x * w0.z + zv.y * w1.z + zv.z * w2.z + zv.w * w3.z;
                acc[i].w += zv.x * w0.w + zv.y * w1.w + zv.z * w2.w + zv.w * w3.w;
            }
        }
        __syncwarp();
#pragma unroll
        for (int i = 0; i < 8; i++) {
            float4 t;
            t.x = fmaxf(acc[i].x, 0.0f); t.y = fmaxf(acc[i].y, 0.0f);
            t.z = fmaxf(acc[i].z, 0.0f); t.w = fmaxf(acc[i].w, 0.0f);
            ((float4*)(zb + i * D))[lane] = t;
        }
        __syncwarp();

        {
            const float4 bb = ((const float4*)b2s)[lane];
#pragma unroll
            for (int i = 0; i < 8; i++) acc[i] = bb;
        }
#pragma unroll 4
        for (int k = 0; k < D; k += 4) {
            const float4 w0 = ((const float4*)(W2s + (k + 0) * D))[lane];
            const float4 w1 = ((const float4*)(W2s + (k + 1) * D))[lane];
            const float4 w2 = ((const float4*)(W2s + (k + 2) * D))[lane];
            const float4 w3 = ((const float4*)(W2s + (k + 3) * D))[lane];
#pragma unroll
            for (int i = 0; i < 8; i++) {
                const float4 zv = *(const float4*)(zb + i * D + k);
                acc[i].x += zv.x * w0.x + zv.y * w1.x + zv.z * w2.x + zv.w * w3.x;
                acc[i].y += zv.x * w0.y + zv.y * w1.y + zv.z * w2.y + zv.w * w3.y;
                acc[i].z += zv.x * w0.z + zv.y * w1.z + zv.z * w2.z + zv.w * w3.z;
                acc[i].w += zv.x * w0.w + zv.y * w1.w + zv.z * w2.w + zv.w * w3.w;
            }
        }
#pragma unroll
        for (int i = 0; i < 8; i++) {
            const int n = base + i;
            float4 u;
            u.x = fmaxf(acc[i].x, 0.0f); u.y = fmaxf(acc[i].y, 0.0f);
            u.z = fmaxf(acc[i].z, 0.0f); u.w = fmaxf(acc[i].w, 0.0f);
            ((float4*)(g_h + (size_t)n * D))[lane] = u;

            const int b = batch[n];
            float* pp = g_pool + (size_t)b * (NL * D) + layer * D + lane * 4;
            atomicAdd(pp + 0, u.x);
            atomicAdd(pp + 1, u.y);
            atomicAdd(pp + 2, u.z);
            atomicAdd(pp + 3, u.w);
        }
        __syncwarp();
    }
}

// ---------------------------------------------------------------------------
// Final MLP
// ---------------------------------------------------------------------------
__global__ void __launch_bounds__(128) final_kernel(
    const float* __restrict__ lin1W, const float* __restrict__ lin1b,
    const float* __restrict__ lin2W, const float* __restrict__ lin2b,
    float* __restrict__ out)
{
    __shared__ float sg[NL * D];
    __shared__ float red[4];
    const int g = blockIdx.x;
    const int tid = threadIdx.x;

    for (int i = tid; i < NL * D; i += 128) sg[i] = g_pool[(size_t)g * NL * D + i];
    __syncthreads();

    float partial = 0.0f;
#pragma unroll
    for (int jj = 0; jj < 3; jj++) {
        const int j = tid + jj * 128;
        float acc = lin1b[j];
        for (int k = 0; k < NL * D; k++)
            acc += sg[k] * lin1W[k * (NL * D) + j];
        partial += fmaxf(acc, 0.0f) * lin2W[j];
    }

    for (int o = 16; o > 0; o >>= 1)
        partial += __shfl_down_sync(0xffffffffu, partial, o);
    if ((tid & 31) == 0) red[tid >> 5] = partial;
    __syncthreads();
    if (tid == 0) out[g] = red[0] + red[1] + red[2] + red[3] + lin2b[0];
}

// ---------------------------------------------------------------------------
extern "C" void kernel_launch(void* const* d_in, const int* in_sizes, int n_in,
                              void* d_out, int out_size)
{
    const float* x    = (const float*)d_in[0];
    const float* ea   = (const float*)d_in[1];
    const float* elW  = (const float*)d_in[2];
    const float* elb  = (const float*)d_in[3];
    const float* W1   = (const float*)d_in[4];
    const float* b1   = (const float*)d_in[5];
    const float* bng  = (const float*)d_in[6];
    const float* bnb  = (const float*)d_in[7];
    const float* bnm  = (const float*)d_in[8];
    const float* bnv  = (const float*)d_in[9];
    const float* W2   = (const float*)d_in[10];
    const float* b2   = (const float*)d_in[11];
    const float* l1W  = (const float*)d_in[12];
    const float* l1b  = (const float*)d_in[13];
    const float* l2W  = (const float*)d_in[14];
    const float* l2b  = (const float*)d_in[15];
    const int* ei     = (const int*)d_in[16];
    const int* batch  = (const int*)d_in[17];
    float* out = (float*)d_out;

    void* deg_p = nullptr;  cudaGetSymbolAddress(&deg_p, g_deg);
    void* cur_p = nullptr;  cudaGetSymbolAddress(&cur_p, g_cursor);
    void* off_p = nullptr;  cudaGetSymbolAddress(&off_p, g_off);
    void* eid_p = nullptr;  cudaGetSymbolAddress(&eid_p, g_eid);
    void* src_p = nullptr;  cudaGetSymbolAddress(&src_p, g_src);
    void* pool_p = nullptr; cudaGetSymbolAddress(&pool_p, g_pool);
    void* h_p    = nullptr; cudaGetSymbolAddress(&h_p, g_h);

    const size_t NODE_SMEM =
        (size_t)(2 * D * D + 3 * D + 16 * 8 * D) * sizeof(float);
    cudaFuncSetAttribute(node_kernel, cudaFuncAttributeMaxDynamicSharedMemorySize,
                         (int)NODE_SMEM);

    // CSR build (segments padded to multiples of 4)
    cudaMemsetAsync(deg_p, 0, NN * sizeof(int), 0);
    cudaMemsetAsync(eid_p, 0, NPADMAX * sizeof(int), 0);
    cudaMemsetAsync(src_p, 0, NPADMAX * sizeof(int), 0);
    hist_kernel<<<(NE + 255) / 256, 256>>>(ei);
    scan1_kernel<<<NBLK, 1024>>>();
    scan2_kernel<<<1, 32>>>();
    scan3_kernel<<<NBLK, 1024>>>();
    cudaMemcpyAsync(cur_p, off_p, NN * sizeof(int), cudaMemcpyDeviceToDevice, 0);
    fill_kernel<<<(NE + 255) / 256, 256>>>(ei);
    permute_kernel<<<(NPADMAX * 4 + 255) / 256, 256>>>(ea);

    cudaMemsetAsync(pool_p, 0, (size_t)NG * NL * D * sizeof(float), 0);

    const float* h = x;
    for (int l = 0; l < NL; l++) {
        aggr_kernel<<<(2 * NN + 7) / 8, 256>>>(h,
            elW + (size_t)l * EF * D, elb + (size_t)l * D);
        node_kernel<<<148, 512, NODE_SMEM>>>(
            W1 + (size_t)l * D * D, b1 + (size_t)l * D,
            bng + (size_t)l * D, bnb + (size_t)l * D,
            bnm + (size_t)l * D, bnv + (size_t)l * D,
            W2 + (size_t)l * D * D, b2 + (size_t)l * D,
            batch, l);
        h = (const float*)h_p;
    }
    final_kernel<<<NG, 128>>>(l1W, l1b, l2W, l2b, out);
}

// round 16
// speedup vs baseline: 1.0332x; 1.0332x over previous
#include <cuda_runtime.h>

#define NN 50000
#define NE 1600000
#define NG 512
#define NL 3
#define D 128
#define EF 16
#define BN_EPS 1e-5f
#define NPADMAX (NE + 4 * NN)   // slots, offsets padded to multiples of 4
#define NBLK 49                 // ceil(NN/1024)

// Scratch (device globals: allocation-free rule)
__device__ float g_h[NN * D];
__device__ float g_z[NN * D];
__device__ float g_pool[NG * NL * D];
__device__ int   g_deg[NN];
__device__ int   g_off[NN + 1];     // padded (mult-of-4) segment starts
__device__ int   g_cursor[NN];
__device__ int   g_eid[NPADMAX];
__device__ int   g_src[NPADMAX];
__device__ float g_attr[(size_t)NPADMAX * EF];   // attr permuted to CSR order
__device__ int   g_bsum[NBLK];
__device__ int   g_boff[NBLK];

#define FMA2(d, a, w) \
    asm("fma.rn.f32x2 %0, %1, %2, %0;" : "+l"(d) : "l"(a), "l"(w))
#define UNPACK2(lo, hi, p) \
    asm("mov.b64 {%0, %1}, %2;" : "=f"(lo), "=f"(hi) : "l"(p))
#define DUP2(d, a) \
    asm("mov.b64 %0, {%1, %1};" : "=l"(d) : "f"(a))

// ---------------------------------------------------------------------------
// CSR build
// ---------------------------------------------------------------------------
__global__ void hist_kernel(const int* __restrict__ ei)
{
    int e = blockIdx.x * blockDim.x + threadIdx.x;
    if (e < NE) atomicAdd(&g_deg[ei[NE + e]], 1);
}

// phase 1: per-1024-chunk exclusive scan of padded degrees
__global__ void scan1_kernel()
{
    __shared__ int buf[1024];
    const int tid = threadIdx.x;
    const int i = blockIdx.x * 1024 + tid;
    const int v = (i < NN) ? ((g_deg[i] + 3) & ~3) : 0;
    buf[tid] = v;
    __syncthreads();
    for (int o = 1; o < 1024; o <<= 1) {
        int t = (tid >= o) ? buf[tid - o] : 0;
        __syncthreads();
        buf[tid] += t;
        __syncthreads();
    }
    if (i < NN) g_off[i] = buf[tid] - v;
    if (tid == 1023) g_bsum[blockIdx.x] = buf[1023];
}

// phase 2: warp scan of the 49 block sums
__global__ void scan2_kernel()
{
    const int tid = threadIdx.x;   // 32 threads
    const int v0 = (2 * tid < NBLK) ? g_bsum[2 * tid] : 0;
    const int v1 = (2 * tid + 1 < NBLK) ? g_bsum[2 * tid + 1] : 0;
    const int ps = v0 + v1;
    int x = ps;
    for (int o = 1; o < 32; o <<= 1) {
        int t = __shfl_up_sync(0xffffffffu, x, o);
        if (tid >= o) x += t;
    }
    const int excl = x - ps;
    if (2 * tid < NBLK) g_boff[2 * tid] = excl;
    if (2 * tid + 1 < NBLK) g_boff[2 * tid + 1] = excl + v0;
    if (tid == 31) g_off[NN] = x;   // total padded slots
}

// phase 3: add block offsets
__global__ void scan3_kernel()
{
    int i = blockIdx.x * 1024 + threadIdx.x;
    if (i < NN) g_off[i] += g_boff[blockIdx.x];
}

__global__ void fill_kernel(const int* __restrict__ ei)
{
    int e = blockIdx.x * blockDim.x + threadIdx.x;
    if (e < NE) {
        int pos = atomicAdd(&g_cursor[ei[NE + e]], 1);
        g_eid[pos] = e;
        g_src[pos] = ei[e];
    }
}

// Permute edge_attr into CSR slot order (64 B/slot, no duplication).
// 4 threads per slot, one float4 each. Pad slots read eid=0 (deterministic).
__global__ void permute_kernel(const float* __restrict__ edge_attr)
{
    const int idx = blockIdx.x * blockDim.x + threadIdx.x;
    const int slot = idx >> 2;
    const int q = idx & 3;
    if (slot >= g_off[NN]) return;
    const int e = g_eid[slot];
    const float4 a = __ldg((const float4*)(edge_attr + (size_t)e * EF) + q);
    ((float4*)(g_attr + (size_t)slot * EF))[q] = a;
}

// ---------------------------------------------------------------------------
// Aggregation: warp per node, 4-edge groups, packed f32x2 edge-linear.
//   z[n] = h[n] + sum_e relu(h[src(e)] + attr(e) @ elW + elb)
// src: sequential aligned int4. attr: uniform LDG.128 (L1 broadcast).
// Weights pre-packed as {w_d0,w_d1},{w_d2,w_d3} pairs; attr duplicated into
// {a,a} at runtime (1 mov) -> 16 packs + 32 FFMA2 instead of 64 FFMA.
// ---------------------------------------------------------------------------
#define EDGE_COMPUTE(hv, slot)                                                \
    {                                                                         \
        const float4* ap = (const float4*)(g_attr + (size_t)(slot) * EF);     \
        const float4 q0 = __ldg(ap + 0);                                      \
        const float4 q1 = __ldg(ap + 1);                                      \
        const float4 q2 = __ldg(ap + 2);                                      \
        const float4 q3 = __ldg(ap + 3);                                      \
        unsigned long long Ea = bq.x, Eb = bq.y;                              \
        const float a[EF] = { q0.x, q0.y, q0.z, q0.w, q1.x, q1.y, q1.z, q1.w,\
                              q2.x, q2.y, q2.z, q2.w, q3.x, q3.y, q3.z, q3.w };\
        _Pragma("unroll")                                                     \
        for (int f = 0; f < EF; f++) {                                        \
            unsigned long long ad;                                            \
            DUP2(ad, a[f]);                                                   \
            FMA2(Ea, ad, wp[f][0]);                                           \
            FMA2(Eb, ad, wp[f][1]);                                           \
        }                                                                     \
        float e0, e1, e2, e3;                                                 \
        UNPACK2(e0, e1, Ea); UNPACK2(e2, e3, Eb);                             \
        acc.x += fmaxf((hv).x + e0, 0.0f);                                    \
        acc.y += fmaxf((hv).y + e1, 0.0f);                                    \
        acc.z += fmaxf((hv).z + e2, 0.0f);                                    \
        acc.w += fmaxf((hv).w + e3, 0.0f);                                    \
    }

__global__ void __launch_bounds__(128) aggr_kernel(
    const float* __restrict__ h,
    const float* __restrict__ elW,   // [EF, D] this layer
    const float* __restrict__ elb)   // [D]
{
    const int lane = threadIdx.x & 31;
    const int warp = threadIdx.x >> 5;
    const int n = blockIdx.x * 4 + warp;
    if (n >= NN) return;

    // Weights packed over dim pairs: wp[f][0]={w_d0,w_d1}, wp[f][1]={w_d2,w_d3}
    unsigned long long wp[EF][2];
#pragma unroll
    for (int f = 0; f < EF; f++) {
        const ulonglong2 w = __ldg((const ulonglong2*)(elW + f * D + lane * 4));
        wp[f][0] = w.x; wp[f][1] = w.y;
    }
    const ulonglong2 bq = __ldg((const ulonglong2*)(elb + lane * 4));

    const int beg = g_off[n];          // multiple of 4
    const int end = beg + g_deg[n];
    float4 acc = make_float4(0.f, 0.f, 0.f, 0.f);

    int idx = beg;
    for (; idx + 4 <= end; idx += 4) {
        const int4 sp = *(const int4*)(g_src + idx);
        const float4 hv0 = __ldg((const float4*)(h + (size_t)sp.x * D) + lane);
        const float4 hv1 = __ldg((const float4*)(h + (size_t)sp.y * D) + lane);
        const float4 hv2 = __ldg((const float4*)(h + (size_t)sp.z * D) + lane);
        const float4 hv3 = __ldg((const float4*)(h + (size_t)sp.w * D) + lane);
        EDGE_COMPUTE(hv0, idx + 0);
        EDGE_COMPUTE(hv1, idx + 1);
        EDGE_COMPUTE(hv2, idx + 2);
        EDGE_COMPUTE(hv3, idx + 3);
    }
    for (; idx < end; idx++) {
        const int src = g_src[idx];
        const float4 hv = __ldg((const float4*)(h + (size_t)src * D) + lane);
        EDGE_COMPUTE(hv, idx);
    }

    const float4 hn = __ldg((const float4*)(h + (size_t)n * D) + lane);
    acc.x += hn.x; acc.y += hn.y; acc.z += hn.z; acc.w += hn.w;
    ((float4*)(g_z + (size_t)n * D))[lane] = acc;
}

// ---------------------------------------------------------------------------
// Node MLP: register-blocked, 8 nodes per warp. BN folded into W1/b1.
// ---------------------------------------------------------------------------
__global__ void __launch_bounds__(512) node_kernel(
    const float* __restrict__ W1, const float* __restrict__ b1,
    const float* __restrict__ bng, const float* __restrict__ bnb,
    const float* __restrict__ bnm, const float* __restrict__ bnv,
    const float* __restrict__ W2, const float* __restrict__ b2,
    const int* __restrict__ batch,
    int layer)
{
    extern __shared__ float sm[];
    float* W1f = sm;
    float* W2s = sm + D * D;
    float* b1f = W2s + D * D;
    float* b2s = b1f + D;
    float* scl = b2s + D;
    float* zbuf = scl + D;

    const int tid = threadIdx.x;

    for (int j = tid; j < D; j += blockDim.x) {
        const float s = bng[j] * rsqrtf(bnv[j] + BN_EPS);
        scl[j] = s;
        b1f[j] = b1[j] * s + (bnb[j] - bnm[j] * s);
        b2s[j] = b2[j];
    }
    __syncthreads();
    for (int i = tid; i < D * D; i += blockDim.x) {
        W1f[i] = W1[i] * scl[i & (D - 1)];
        W2s[i] = W2[i];
    }
    __syncthreads();

    const int lane = tid & 31;
    const int warp = tid >> 5;
    float* zb = zbuf + warp * 8 * D;

    const int gw = blockIdx.x * 16 + warp;
    const int nw = gridDim.x * 16;

    for (int base = gw * 8; base < NN; base += nw * 8) {
#pragma unroll
        for (int i = 0; i < 8; i++) {
            const float4 v = __ldg((const float4*)(g_z + (size_t)(base + i) * D) + lane);
            ((float4*)(zb + i * D))[lane] = v;
        }
        __syncwarp();

        float4 acc[8];
        {
            const float4 bb = ((const float4*)b1f)[lane];
#pragma unroll
            for (int i = 0; i < 8; i++) acc[i] = bb;
        }
#pragma unroll 4
        for (int k = 0; k < D; k += 4) {
            const float4 w0 = ((const float4*)(W1f + (k + 0) * D))[lane];
            const float4 w1 = ((const float4*)(W1f + (k + 1) * D))[lane];
            const float4 w2 = ((const float4*)(W1f + (k + 2) * D))[lane];
            const float4 w3 = ((const float4*)(W1f + (k + 3) * D))[lane];
#pragma unroll
            for (int i = 0; i < 8; i++) {
                const float4 zv = *(const float4*)(zb + i * D + k);
                acc[i].x += zv.x * w0.x + zv.y * w1.x + zv.z * w2.x + zv.w * w3.x;
                acc[i].y += zv.x * w0.y + zv.y * w1.y + zv.z * w2.y + zv.w * w3.y;
                acc[i].z += zv.x * w0.z + zv.y * w1.z + zv.z * w2.z + zv.w * w3.z;
                acc[i].w += zv.x * w0.w + zv.y * w1.w + zv.z * w2.w + zv.w * w3.w;
            }
        }
        __syncwarp();
#pragma unroll
        for (int i = 0; i < 8; i++) {
            float4 t;
            t.x = fmaxf(acc[i].x, 0.0f); t.y = fmaxf(acc[i].y, 0.0f);
            t.z = fmaxf(acc[i].z, 0.0f); t.w = fmaxf(acc[i].w, 0.0f);
            ((float4*)(zb + i * D))[lane] = t;
        }
        __syncwarp();

        {
            const float4 bb = ((const float4*)b2s)[lane];
#pragma unroll
            for (int i = 0; i < 8; i++) acc[i] = bb;
        }
#pragma unroll 4
        for (int k = 0; k < D; k += 4) {
            const float4 w0 = ((const float4*)(W2s + (k + 0) * D))[lane];
            const float4 w1 = ((const float4*)(W2s + (k + 1) * D))[lane];
            const float4 w2 = ((const float4*)(W2s + (k + 2) * D))[lane];
            const float4 w3 = ((const float4*)(W2s + (k + 3) * D))[lane];
#pragma unroll
            for (int i = 0; i < 8; i++) {
                const float4 zv = *(const float4*)(zb + i * D + k);
                acc[i].x += zv.x * w0.x + zv.y * w1.x + zv.z * w2.x + zv.w * w3.x;
                acc[i].y += zv.x * w0.y + zv.y * w1.y + zv.z * w2.y + zv.w * w3.y;
                acc[i].z += zv.x * w0.z + zv.y * w1.z + zv.z * w2.z + zv.w * w3.z;
                acc[i].w += zv.x * w0.w + zv.y * w1.w + zv.z * w2.w + zv.w * w3.w;
            }
        }
#pragma unroll
        for (int i = 0; i < 8; i++) {
            const int n = base + i;
            float4 u;
            u.x = fmaxf(acc[i].x, 0.0f); u.y = fmaxf(acc[i].y, 0.0f);
            u.z = fmaxf(acc[i].z, 0.0f); u.w = fmaxf(acc[i].w, 0.0f);
            ((float4*)(g_h + (size_t)n * D))[lane] = u;

            const int b = batch[n];
            float* pp = g_pool + (size_t)b * (NL * D) + layer * D + lane * 4;
            atomicAdd(pp + 0, u.x);
            atomicAdd(pp + 1, u.y);
            atomicAdd(pp + 2, u.z);
            atomicAdd(pp + 3, u.w);
        }
        __syncwarp();
    }
}

// ---------------------------------------------------------------------------
// Final MLP
// ---------------------------------------------------------------------------
__global__ void __launch_bounds__(128) final_kernel(
    const float* __restrict__ lin1W, const float* __restrict__ lin1b,
    const float* __restrict__ lin2W, const float* __restrict__ lin2b,
    float* __restrict__ out)
{
    __shared__ float sg[NL * D];
    __shared__ float red[4];
    const int g = blockIdx.x;
    const int tid = threadIdx.x;

    for (int i = tid; i < NL * D; i += 128) sg[i] = g_pool[(size_t)g * NL * D + i];
    __syncthreads();

    float partial = 0.0f;
#pragma unroll
    for (int jj = 0; jj < 3; jj++) {
        const int j = tid + jj * 128;
        float acc = lin1b[j];
        for (int k = 0; k < NL * D; k++)
            acc += sg[k] * lin1W[k * (NL * D) + j];
        partial += fmaxf(acc, 0.0f) * lin2W[j];
    }

    for (int o = 16; o > 0; o >>= 1)
        partial += __shfl_down_sync(0xffffffffu, partial, o);
    if ((tid & 31) == 0) red[tid >> 5] = partial;
    __syncthreads();
    if (tid == 0) out[g] = red[0] + red[1] + red[2] + red[3] + lin2b[0];
}

// ---------------------------------------------------------------------------
extern "C" void kernel_launch(void* const* d_in, const int* in_sizes, int n_in,
                              void* d_out, int out_size)
{
    const float* x    = (const float*)d_in[0];
    const float* ea   = (const float*)d_in[1];
    const float* elW  = (const float*)d_in[2];
    const float* elb  = (const float*)d_in[3];
    const float* W1   = (const float*)d_in[4];
    const float* b1   = (const float*)d_in[5];
    const float* bng  = (const float*)d_in[6];
    const float* bnb  = (const float*)d_in[7];
    const float* bnm  = (const float*)d_in[8];
    const float* bnv  = (const float*)d_in[9];
    const float* W2   = (const float*)d_in[10];
    const float* b2   = (const float*)d_in[11];
    const float* l1W  = (const float*)d_in[12];
    const float* l1b  = (const float*)d_in[13];
    const float* l2W  = (const float*)d_in[14];
    const float* l2b  = (const float*)d_in[15];
    const int* ei     = (const int*)d_in[16];
    const int* batch  = (const int*)d_in[17];
    float* out = (float*)d_out;

    void* deg_p = nullptr;  cudaGetSymbolAddress(&deg_p, g_deg);
    void* cur_p = nullptr;  cudaGetSymbolAddress(&cur_p, g_cursor);
    void* off_p = nullptr;  cudaGetSymbolAddress(&off_p, g_off);
    void* eid_p = nullptr;  cudaGetSymbolAddress(&eid_p, g_eid);
    void* src_p = nullptr;  cudaGetSymbolAddress(&src_p, g_src);
    void* pool_p = nullptr; cudaGetSymbolAddress(&pool_p, g_pool);
    void* h_p    = nullptr; cudaGetSymbolAddress(&h_p, g_h);

    const size_t NODE_SMEM =
        (size_t)(2 * D * D + 3 * D + 16 * 8 * D) * sizeof(float);
    cudaFuncSetAttribute(node_kernel, cudaFuncAttributeMaxDynamicSharedMemorySize,
                         (int)NODE_SMEM);

    // CSR build (segments padded to multiples of 4)
    cudaMemsetAsync(deg_p, 0, NN * sizeof(int), 0);
    cudaMemsetAsync(eid_p, 0, NPADMAX * sizeof(int), 0);
    cudaMemsetAsync(src_p, 0, NPADMAX * sizeof(int), 0);
    hist_kernel<<<(NE + 255) / 256, 256>>>(ei);
    scan1_kernel<<<NBLK, 1024>>>();
    scan2_kernel<<<1, 32>>>();
    scan3_kernel<<<NBLK, 1024>>>();
    cudaMemcpyAsync(cur_p, off_p, NN * sizeof(int), cudaMemcpyDeviceToDevice, 0);
    fill_kernel<<<(NE + 255) / 256, 256>>>(ei);
    permute_kernel<<<(NPADMAX * 4 + 255) / 256, 256>>>(ea);

    cudaMemsetAsync(pool_p, 0, (size_t)NG * NL * D * sizeof(float), 0);

    const float* h = x;
    for (int l = 0; l < NL; l++) {
        aggr_kernel<<<(NN + 3) / 4, 128>>>(h,
            elW + (size_t)l * EF * D, elb + (size_t)l * D);
        node_kernel<<<148, 512, NODE_SMEM>>>(
            W1 + (size_t)l * D * D, b1 + (size_t)l * D,
            bng + (size_t)l * D, bnb + (size_t)l * D,
            bnm + (size_t)l * D, bnv + (size_t)l * D,
            W2 + (size_t)l * D * D, b2 + (size_t)l * D,
            batch, l);
        h = (const float*)h_p;
    }
    final_kernel<<<NG, 128>>>(l1W, l1b, l2W, l2b, out);
}

// round 17
// speedup vs baseline: 1.3702x; 1.3262x over previous
#include <cuda_runtime.h>

#define NN 50000
#define NE 1600000
#define NG 512
#define NL 3
#define D 128
#define EF 16
#define BN_EPS 1e-5f
#define NPADMAX (NE + 4 * NN)   // slots, offsets padded to multiples of 4
#define NBLK 49                 // ceil(NN/1024)

// Scratch (device globals: allocation-free rule)
__device__ float g_h[NN * D];
__device__ float g_z[NN * D];
__device__ float g_pool[NG * NL * D];
__device__ int   g_deg[NN];
__device__ int   g_off[NN + 1];     // padded (mult-of-4) segment starts
__device__ int   g_cursor[NN];
__device__ int   g_eid[NPADMAX];
__device__ int   g_src[NPADMAX];
__device__ float g_attr[(size_t)NPADMAX * EF];   // attr permuted to CSR order
__device__ int   g_bsum[NBLK];
__device__ int   g_boff[NBLK];
__device__ int   g_ctr[NL];         // dynamic work counters (one per layer)

// ---------------------------------------------------------------------------
// CSR build
// ---------------------------------------------------------------------------
__global__ void hist_kernel(const int* __restrict__ ei)
{
    int e = blockIdx.x * blockDim.x + threadIdx.x;
    if (e < NE) atomicAdd(&g_deg[ei[NE + e]], 1);
}

// phase 1: per-1024-chunk exclusive scan of padded degrees
__global__ void scan1_kernel()
{
    __shared__ int buf[1024];
    const int tid = threadIdx.x;
    const int i = blockIdx.x * 1024 + tid;
    const int v = (i < NN) ? ((g_deg[i] + 3) & ~3) : 0;
    buf[tid] = v;
    __syncthreads();
    for (int o = 1; o < 1024; o <<= 1) {
        int t = (tid >= o) ? buf[tid - o] : 0;
        __syncthreads();
        buf[tid] += t;
        __syncthreads();
    }
    if (i < NN) g_off[i] = buf[tid] - v;
    if (tid == 1023) g_bsum[blockIdx.x] = buf[1023];
}

// phase 2: warp scan of the 49 block sums
__global__ void scan2_kernel()
{
    const int tid = threadIdx.x;   // 32 threads
    const int v0 = (2 * tid < NBLK) ? g_bsum[2 * tid] : 0;
    const int v1 = (2 * tid + 1 < NBLK) ? g_bsum[2 * tid + 1] : 0;
    const int ps = v0 + v1;
    int x = ps;
    for (int o = 1; o < 32; o <<= 1) {
        int t = __shfl_up_sync(0xffffffffu, x, o);
        if (tid >= o) x += t;
    }
    const int excl = x - ps;
    if (2 * tid < NBLK) g_boff[2 * tid] = excl;
    if (2 * tid + 1 < NBLK) g_boff[2 * tid + 1] = excl + v0;
    if (tid == 31) g_off[NN] = x;   // total padded slots
}

// phase 3: add block offsets
__global__ void scan3_kernel()
{
    int i = blockIdx.x * 1024 + threadIdx.x;
    if (i < NN) g_off[i] += g_boff[blockIdx.x];
}

__global__ void fill_kernel(const int* __restrict__ ei)
{
    int e = blockIdx.x * blockDim.x + threadIdx.x;
    if (e < NE) {
        int pos = atomicAdd(&g_cursor[ei[NE + e]], 1);
        g_eid[pos] = e;
        g_src[pos] = ei[e];
    }
}

// Permute edge_attr into CSR slot order (64 B/slot, no duplication).
// 4 threads per slot, one float4 each. Pad slots hold garbage eids -> guarded
// (their attr is never read by aggr, and OOB reads are skipped).
__global__ void permute_kernel(const float* __restrict__ edge_attr)
{
    const int idx = blockIdx.x * blockDim.x + threadIdx.x;
    const int slot = idx >> 2;
    const int q = idx & 3;
    if (slot >= g_off[NN]) return;
    const unsigned int e = (unsigned int)g_eid[slot];
    if (e >= NE) return;   // uninitialized pad slot
    const float4 a = __ldg((const float4*)(edge_attr + (size_t)e * EF) + q);
    ((float4*)(g_attr + (size_t)slot * EF))[q] = a;
}

// ---------------------------------------------------------------------------
// Aggregation: persistent warps, dynamic node stealing, 4-edge groups.
//   z[n] = h[n] + sum_e relu(h[src(e)] + attr(e) @ elW + elb)
// src: sequential aligned int4. attr: uniform LDG.128 (L1 broadcast).
// ---------------------------------------------------------------------------
#define EDGE_COMPUTE(hv, slot)                                                \
    {                                                                         \
        const float4* ap = (const float4*)(g_attr + (size_t)(slot) * EF);     \
        const float4 q0 = __ldg(ap + 0);                                      \
        const float4 q1 = __ldg(ap + 1);                                      \
        const float4 q2 = __ldg(ap + 2);                                      \
        const float4 q3 = __ldg(ap + 3);                                      \
        float e0 = br[0], e1 = br[1], e2 = br[2], e3 = br[3];                 \
        const float a[EF] = { q0.x, q0.y, q0.z, q0.w, q1.x, q1.y, q1.z, q1.w,\
                              q2.x, q2.y, q2.z, q2.w, q3.x, q3.y, q3.z, q3.w };\
        _Pragma("unroll")                                                     \
        for (int f = 0; f < EF; f++) {                                        \
            e0 += a[f] * wr[f][0];                                            \
            e1 += a[f] * wr[f][1];                                            \
            e2 += a[f] * wr[f][2];                                            \
            e3 += a[f] * wr[f][3];                                            \
        }                                                                     \
        acc.x += fmaxf((hv).x + e0, 0.0f);                                    \
        acc.y += fmaxf((hv).y + e1, 0.0f);                                    \
        acc.z += fmaxf((hv).z + e2, 0.0f);                                    \
        acc.w += fmaxf((hv).w + e3, 0.0f);                                    \
    }

__global__ void __launch_bounds__(128) aggr_kernel(
    const float* __restrict__ h,
    const float* __restrict__ elW,   // [EF, D] this layer
    const float* __restrict__ elb,   // [D]
    int layer)
{
    const int lane = threadIdx.x & 31;

    float wr[EF][4];
    float br[4];
    {
        const float4 bb = ((const float4*)elb)[lane];
        br[0] = bb.x; br[1] = bb.y; br[2] = bb.z; br[3] = bb.w;
#pragma unroll
        for (int f = 0; f < EF; f++) {
            const float4 w = ((const float4*)(elW + f * D))[lane];
            wr[f][0] = w.x; wr[f][1] = w.y; wr[f][2] = w.z; wr[f][3] = w.w;
        }
    }

    int* ctr = &g_ctr[layer];
    for (;;) {
        int n;
        if (lane == 0) n = atomicAdd(ctr, 1);
        n = __shfl_sync(0xffffffffu, n, 0);
        if (n >= NN) break;

        const int beg = g_off[n];          // multiple of 4
        const int end = beg + g_deg[n];
        float4 acc = make_float4(0.f, 0.f, 0.f, 0.f);

        int idx = beg;
        for (; idx + 4 <= end; idx += 4) {
            const int4 sp = *(const int4*)(g_src + idx);
            const float4 hv0 = __ldg((const float4*)(h + (size_t)sp.x * D) + lane);
            const float4 hv1 = __ldg((const float4*)(h + (size_t)sp.y * D) + lane);
            const float4 hv2 = __ldg((const float4*)(h + (size_t)sp.z * D) + lane);
            const float4 hv3 = __ldg((const float4*)(h + (size_t)sp.w * D) + lane);
            EDGE_COMPUTE(hv0, idx + 0);
            EDGE_COMPUTE(hv1, idx + 1);
            EDGE_COMPUTE(hv2, idx + 2);
            EDGE_COMPUTE(hv3, idx + 3);
        }
        for (; idx < end; idx++) {
            const int src = g_src[idx];
            const float4 hv = __ldg((const float4*)(h + (size_t)src * D) + lane);
            EDGE_COMPUTE(hv, idx);
        }

        const float4 hn = __ldg((const float4*)(h + (size_t)n * D) + lane);
        acc.x += hn.x; acc.y += hn.y; acc.z += hn.z; acc.w += hn.w;
        ((float4*)(g_z + (size_t)n * D))[lane] = acc;
    }
}

// ---------------------------------------------------------------------------
// Node MLP: register-blocked, 8 nodes per warp. BN folded into W1/b1.
// ---------------------------------------------------------------------------
__global__ void __launch_bounds__(512) node_kernel(
    const float* __restrict__ W1, const float* __restrict__ b1,
    const float* __restrict__ bng, const float* __restrict__ bnb,
    const float* __restrict__ bnm, const float* __restrict__ bnv,
    const float* __restrict__ W2, const float* __restrict__ b2,
    const int* __restrict__ batch,
    int layer)
{
    extern __shared__ float sm[];
    float* W1f = sm;
    float* W2s = sm + D * D;
    float* b1f = W2s + D * D;
    float* b2s = b1f + D;
    float* scl = b2s + D;
    float* zbuf = scl + D;

    const int tid = threadIdx.x;

    for (int j = tid; j < D; j += blockDim.x) {
        const float s = bng[j] * rsqrtf(bnv[j] + BN_EPS);
        scl[j] = s;
        b1f[j] = b1[j] * s + (bnb[j] - bnm[j] * s);
        b2s[j] = b2[j];
    }
    __syncthreads();
    for (int i = tid; i < D * D; i += blockDim.x) {
        W1f[i] = W1[i] * scl[i & (D - 1)];
        W2s[i] = W2[i];
    }
    __syncthreads();

    const int lane = tid & 31;
    const int warp = tid >> 5;
    float* zb = zbuf + warp * 8 * D;

    const int gw = blockIdx.x * 16 + warp;
    const int nw = gridDim.x * 16;

    for (int base = gw * 8; base < NN; base += nw * 8) {
#pragma unroll
        for (int i = 0; i < 8; i++) {
            const float4 v = __ldg((const float4*)(g_z + (size_t)(base + i) * D) + lane);
            ((float4*)(zb + i * D))[lane] = v;
        }
        __syncwarp();

        float4 acc[8];
        {
            const float4 bb = ((const float4*)b1f)[lane];
#pragma unroll
            for (int i = 0; i < 8; i++) acc[i] = bb;
        }
#pragma unroll 4
        for (int k = 0; k < D; k += 4) {
            const float4 w0 = ((const float4*)(W1f + (k + 0) * D))[lane];
            const float4 w1 = ((const float4*)(W1f + (k + 1) * D))[lane];
            const float4 w2 = ((const float4*)(W1f + (k + 2) * D))[lane];
            const float4 w3 = ((const float4*)(W1f + (k + 3) * D))[lane];
#pragma unroll
            for (int i = 0; i < 8; i++) {
                const float4 zv = *(const float4*)(zb + i * D + k);
                acc[i].x += zv.x * w0.x + zv.y * w1.x + zv.z * w2.x + zv.w * w3.x;
                acc[i].y += zv.x * w0.y + zv.y * w1.y + zv.z * w2.y + zv.w * w3.y;
                acc[i].z += zv.x * w0.z + zv.y * w1.z + zv.z * w2.z + zv.w * w3.z;
                acc[i].w += zv.x * w0.w + zv.y * w1.w + zv.z * w2.w + zv.w * w3.w;
            }
        }
        __syncwarp();
#pragma unroll
        for (int i = 0; i < 8; i++) {
            float4 t;
            t.x = fmaxf(acc[i].x, 0.0f); t.y = fmaxf(acc[i].y, 0.0f);
            t.z = fmaxf(acc[i].z, 0.0f); t.w = fmaxf(acc[i].w, 0.0f);
            ((float4*)(zb + i * D))[lane] = t;
        }
        __syncwarp();

        {
            const float4 bb = ((const float4*)b2s)[lane];
#pragma unroll
            for (int i = 0; i < 8; i++) acc[i] = bb;
        }
#pragma unroll 4
        for (int k = 0; k < D; k += 4) {
            const float4 w0 = ((const float4*)(W2s + (k + 0) * D))[lane];
            const float4 w1 = ((const float4*)(W2s + (k + 1) * D))[lane];
            const float4 w2 = ((const float4*)(W2s + (k + 2) * D))[lane];
            const float4 w3 = ((const float4*)(W2s + (k + 3) * D))[lane];
#pragma unroll
            for (int i = 0; i < 8; i++) {
                const float4 zv = *(const float4*)(zb + i * D + k);
                acc[i].x += zv.x * w0.x + zv.y * w1.x + zv.z * w2.x + zv.w * w3.x;
                acc[i].y += zv.x * w0.y + zv.y * w1.y + zv.z * w2.y + zv.w * w3.y;
                acc[i].z += zv.x * w0.z + zv.y * w1.z + zv.z * w2.z + zv.w * w3.z;
                acc[i].w += zv.x * w0.w + zv.y * w1.w + zv.z * w2.w + zv.w * w3.w;
            }
        }
#pragma unroll
        for (int i = 0; i < 8; i++) {
            const int n = base + i;
            float4 u;
            u.x = fmaxf(acc[i].x, 0.0f); u.y = fmaxf(acc[i].y, 0.0f);
            u.z = fmaxf(acc[i].z, 0.0f); u.w = fmaxf(acc[i].w, 0.0f);
            ((float4*)(g_h + (size_t)n * D))[lane] = u;

            const int b = batch[n];
            float* pp = g_pool + (size_t)b * (NL * D) + layer * D + lane * 4;
            atomicAdd(pp + 0, u.x);
            atomicAdd(pp + 1, u.y);
            atomicAdd(pp + 2, u.z);
            atomicAdd(pp + 3, u.w);
        }
        __syncwarp();
    }
}

// ---------------------------------------------------------------------------
// Final MLP
// ---------------------------------------------------------------------------
__global__ void __launch_bounds__(128) final_kernel(
    const float* __restrict__ lin1W, const float* __restrict__ lin1b,
    const float* __restrict__ lin2W, const float* __restrict__ lin2b,
    float* __restrict__ out)
{
    __shared__ float sg[NL * D];
    __shared__ float red[4];
    const int g = blockIdx.x;
    const int tid = threadIdx.x;

    for (int i = tid; i < NL * D; i += 128) sg[i] = g_pool[(size_t)g * NL * D + i];
    __syncthreads();

    float partial = 0.0f;
#pragma unroll
    for (int jj = 0; jj < 3; jj++) {
        const int j = tid + jj * 128;
        float acc = lin1b[j];
        for (int k = 0; k < NL * D; k++)
            acc += sg[k] * lin1W[k * (NL * D) + j];
        partial += fmaxf(acc, 0.0f) * lin2W[j];
    }

    for (int o = 16; o > 0; o >>= 1)
        partial += __shfl_down_sync(0xffffffffu, partial, o);
    if ((tid & 31) == 0) red[tid >> 5] = partial;
    __syncthreads();
    if (tid == 0) out[g] = red[0] + red[1] + red[2] + red[3] + lin2b[0];
}

// ---------------------------------------------------------------------------
extern "C" void kernel_launch(void* const* d_in, const int* in_sizes, int n_in,
                              void* d_out, int out_size)
{
    const float* x    = (const float*)d_in[0];
    const float* ea   = (const float*)d_in[1];
    const float* elW  = (const float*)d_in[2];
    const float* elb  = (const float*)d_in[3];
    const float* W1   = (const float*)d_in[4];
    const float* b1   = (const float*)d_in[5];
    const float* bng  = (const float*)d_in[6];
    const float* bnb  = (const float*)d_in[7];
    const float* bnm  = (const float*)d_in[8];
    const float* bnv  = (const float*)d_in[9];
    const float* W2   = (const float*)d_in[10];
    const float* b2   = (const float*)d_in[11];
    const float* l1W  = (const float*)d_in[12];
    const float* l1b  = (const float*)d_in[13];
    const float* l2W  = (const float*)d_in[14];
    const float* l2b  = (const float*)d_in[15];
    const int* ei     = (const int*)d_in[16];
    const int* batch  = (const int*)d_in[17];
    float* out = (float*)d_out;

    void* deg_p = nullptr;  cudaGetSymbolAddress(&deg_p, g_deg);
    void* cur_p = nullptr;  cudaGetSymbolAddress(&cur_p, g_cursor);
    void* off_p = nullptr;  cudaGetSymbolAddress(&off_p, g_off);
    void* pool_p = nullptr; cudaGetSymbolAddress(&pool_p, g_pool);
    void* ctr_p  = nullptr; cudaGetSymbolAddress(&ctr_p, g_ctr);
    void* h_p    = nullptr; cudaGetSymbolAddress(&h_p, g_h);

    const size_t NODE_SMEM =
        (size_t)(2 * D * D + 3 * D + 16 * 8 * D) * sizeof(float);
    cudaFuncSetAttribute(node_kernel, cudaFuncAttributeMaxDynamicSharedMemorySize,
                         (int)NODE_SMEM);

    // CSR build (segments padded to multiples of 4; pad slots guarded, no memset)
    cudaMemsetAsync(deg_p, 0, NN * sizeof(int), 0);
    cudaMemsetAsync(ctr_p, 0, NL * sizeof(int), 0);
    hist_kernel<<<(NE + 255) / 256, 256>>>(ei);
    scan1_kernel<<<NBLK, 1024>>>();
    scan2_kernel<<<1, 32>>>();
    scan3_kernel<<<NBLK, 1024>>>();
    cudaMemcpyAsync(cur_p, off_p, NN * sizeof(int), cudaMemcpyDeviceToDevice, 0);
    fill_kernel<<<(NE + 255) / 256, 256>>>(ei);
    permute_kernel<<<(NPADMAX * 4 + 255) / 256, 256>>>(ea);

    cudaMemsetAsync(pool_p, 0, (size_t)NG * NL * D * sizeof(float), 0);

    const float* h = x;
    for (int l = 0; l < NL; l++) {
        aggr_kernel<<<592, 128>>>(h,
            elW + (size_t)l * EF * D, elb + (size_t)l * D, l);
        node_kernel<<<148, 512, NODE_SMEM>>>(
            W1 + (size_t)l * D * D, b1 + (size_t)l * D,
            bng + (size_t)l * D, bnb + (size_t)l * D,
            bnm + (size_t)l * D, bnv + (size_t)l * D,
            W2 + (size_t)l * D * D, b2 + (size_t)l * D,
            batch, l);
        h = (const float*)h_p;
    }
    final_kernel<<<NG, 128>>>(l1W, l1b, l2W, l2b, out);
}